// round 10
// baseline (speedup 1.0000x reference)
#include <cuda_runtime.h>
#include <cuda_fp16.h>
#include <math.h>
#include <stdint.h>

#define ED 1024
#define NB 2
#define SEQ 4096
#define MTOT (NB * SEQ)

// ---------------- scratch (static device globals; no allocs allowed) -------
__device__ __half g_xh [(size_t)MTOT * ED];            // x rounded to fp16
__device__ __half g_Whi[4][(size_t)ED * ED];           // q,k,v,o weight hi
__device__ __half g_Wlo[4][(size_t)ED * ED];           // q,k,v,o weight lo
__device__ __half g_Qp [(size_t)MTOT * ED];            // Q plain fp16
__device__ __half g_Khi[(size_t)MTOT * ED];
__device__ __half g_Klo[(size_t)MTOT * ED];
__device__ __half g_Vhi[(size_t)MTOT * ED];            // natural [b][s][d]
__device__ __half g_Vlo[(size_t)MTOT * ED];
__device__ __half g_Op [(size_t)MTOT * ED];            // O plain fp16
__device__ float  g_S  [(size_t)NB * SEQ * SEQ];
__device__ __half g_Phi[(size_t)NB * SEQ * SEQ];

// ---------------- PTX helpers ---------------------------------------------
__device__ __forceinline__ uint32_t smem_u32(const void* p) {
    uint32_t a;
    asm("{ .reg .u64 t; cvta.to.shared.u64 t, %1; cvt.u32.u64 %0, t; }" : "=r"(a) : "l"(p));
    return a;
}
__device__ __forceinline__ void cp16(uint32_t dst, const void* src) {
    asm volatile("cp.async.cg.shared.global [%0], [%1], 16;" :: "r"(dst), "l"(src));
}
#define CP_COMMIT() asm volatile("cp.async.commit_group;" ::: "memory")

__device__ __forceinline__ void ldsm4(uint32_t* r, uint32_t addr) {
    asm volatile("ldmatrix.sync.aligned.m8n8.x4.shared.b16 {%0,%1,%2,%3}, [%4];"
                 : "=r"(r[0]), "=r"(r[1]), "=r"(r[2]), "=r"(r[3]) : "r"(addr));
}
__device__ __forceinline__ void ldsm4t(uint32_t* r, uint32_t addr) {
    asm volatile("ldmatrix.sync.aligned.m8n8.x4.trans.shared.b16 {%0,%1,%2,%3}, [%4];"
                 : "=r"(r[0]), "=r"(r[1]), "=r"(r[2]), "=r"(r[3]) : "r"(addr));
}
__device__ __forceinline__ void mma16816(float* c, const uint32_t* a, const uint32_t* b) {
    asm volatile(
        "mma.sync.aligned.m16n8k16.row.col.f32.f16.f16.f32 "
        "{%0,%1,%2,%3}, {%4,%5,%6,%7}, {%8,%9}, {%0,%1,%2,%3};\n"
        : "+f"(c[0]), "+f"(c[1]), "+f"(c[2]), "+f"(c[3])
        : "r"(a[0]), "r"(a[1]), "r"(a[2]), "r"(a[3]), "r"(b[0]), "r"(b[1]));
}
__device__ __forceinline__ void split1h(float v, __half& h, __half& l) {
    h = __float2half_rn(v);
    l = __float2half_rn(v - __half2float(h));
}

// ---------------- GEMM config ----------------------------------------------
// Block 128(M) x 128(N) x 32(K). 8 warps (2M x 4N), warp tile 64x32.
// 4-stage cp.async ring (24 KB/stage = 96 KB) -> 2 CTAs/SM, <=128 regs.
// ONE barrier per iteration: load for stage t+3 reuses the buffer whose
// reads finished at t-1 (guaranteed by the top-of-iter barrier).
// A plain fp16; B split hi/lo (2 passes).
// TRANSB=0: B is [N,K] k-major. TRANSB=1: B is [K,N] (V natural layout).
// MODE 0: fp32*alpha   MODE 1: split fp16 (Chi+Clo)   MODE 2: plain fp16 (Chi)
#define BM 128
#define BN 128
#define BK 32
#define NSTG 4
#define A_T  ((uint32_t)(BM * BK * 2))          // 8 KB
#define B_T  ((uint32_t)(BN * BK * 2))          // 8 KB per half-tile
#define STG_B (A_T + 2u * B_T)                  // 24 KB per stage
#define GSMEM ((uint32_t)NSTG * STG_B)          // 96 KB -> 2 CTAs/SM

// 64B rows (32 halves), 16B chunk c in 0..3
__device__ __forceinline__ uint32_t swz64(int r, int c) {
    return (uint32_t)(r * 64 + ((c ^ ((r >> 1) & 3)) << 4));
}
// 256B rows (128 halves), 16B chunk c in 0..15
__device__ __forceinline__ uint32_t swzT(int r, int c) {
    return (uint32_t)(r * 256 + ((c ^ (r & 7)) << 4));
}

template <int TRANSB>
__device__ __forceinline__ void load_stage_g(
    uint32_t s0, const __half* __restrict__ Ap,
    const __half* __restrict__ Bhi, const __half* __restrict__ Blo,
    size_t rowA0, size_t rowB0, int N, int K, int k0, int tid)
{
#pragma unroll
    for (int i = 0; i < 2; i++) {               // A: 128 rows x 4 chunks = 512
        int idx = tid + i * 256;
        int r = idx >> 2, c = idx & 3;
        cp16(s0 + swz64(r, c), Ap + (rowA0 + r) * (size_t)K + k0 + c * 8);
    }
#pragma unroll
    for (int h = 0; h < 2; h++) {
        const __half* g = h ? Blo : Bhi;
        uint32_t d0 = s0 + A_T + h * B_T;
        if (!TRANSB) {
#pragma unroll
            for (int i = 0; i < 2; i++) {       // 128 rows x 4 chunks = 512
                int idx = tid + i * 256;
                int r = idx >> 2, c = idx & 3;
                cp16(d0 + swz64(r, c), g + (rowB0 + r) * (size_t)K + k0 + c * 8);
            }
        } else {
#pragma unroll
            for (int i = 0; i < 2; i++) {       // 32 rows x 16 chunks = 512
                int idx = tid + i * 256;
                int r = idx >> 4, c = idx & 15;
                cp16(d0 + swzT(r, c), g + (size_t)(k0 + r) * N + rowB0 + c * 8);
            }
        }
    }
    CP_COMMIT();
}

template <int MODE, int TRANSB>
__global__ __launch_bounds__(256, 2) void gemm_fp16x2(
    const __half* __restrict__ Ap,
    const __half* __restrict__ Bhi, const __half* __restrict__ Blo,
    float* __restrict__ Cf, __half* __restrict__ Chi, __half* __restrict__ Clo,
    int N, int K, float alpha, size_t sA, size_t sB, size_t sC)
{
    extern __shared__ char smem[];
    const uint32_t sb = smem_u32(smem);
    const int tid = threadIdx.x, lane = tid & 31, wid = tid >> 5;
    const int wm = wid >> 2, wn = wid & 3;
    const int bz = blockIdx.z;
    Ap  += (size_t)bz * sA;
    Bhi += (size_t)bz * sB; Blo += (size_t)bz * sB;
    const size_t rowA0 = (size_t)blockIdx.y * BM;
    const size_t rowB0 = (size_t)blockIdx.x * BN;

    float acc[4][4][4];
#pragma unroll
    for (int a = 0; a < 4; a++)
#pragma unroll
        for (int b = 0; b < 4; b++)
#pragma unroll
            for (int k = 0; k < 4; k++) acc[a][b][k] = 0.0f;

    const int T = K / BK;
    load_stage_g<TRANSB>(sb + 0 * STG_B, Ap, Bhi, Blo, rowA0, rowB0, N, K, 0 * BK, tid);
    load_stage_g<TRANSB>(sb + 1 * STG_B, Ap, Bhi, Blo, rowA0, rowB0, N, K, 1 * BK, tid);
    load_stage_g<TRANSB>(sb + 2 * STG_B, Ap, Bhi, Blo, rowA0, rowB0, N, K, 2 * BK, tid);

    for (int t = 0; t < T; t++) {
        // Wait until stage t is complete (exact count at the tail).
        if (t + 2 < T)
            asm volatile("cp.async.wait_group 2;" ::: "memory");
        else if (t + 1 < T)
            asm volatile("cp.async.wait_group 1;" ::: "memory");
        else
            asm volatile("cp.async.wait_group 0;" ::: "memory");
        __syncthreads();   // stage t ready AND all warps done reading stage t-1

        // Issue the next load immediately (writes buffer freed at t-1).
        if (t + 3 < T)
            load_stage_g<TRANSB>(sb + (uint32_t)((t + 3) & 3) * STG_B,
                                 Ap, Bhi, Blo, rowA0, rowB0, N, K,
                                 (t + 3) * BK, tid);

        const uint32_t s0 = sb + (uint32_t)(t & 3) * STG_B;
#pragma unroll
        for (int st = 0; st < 2; st++) {
            uint32_t ah[4][4], bh[4][2], bl[4][2];
            // ---- A fragments ----
            const int ra = lane & 15;
            const int ca = 2 * st + (lane >> 4);
#pragma unroll
            for (int mf = 0; mf < 4; mf++) {
                int r = wm * 64 + mf * 16 + ra;
                ldsm4(ah[mf], s0 + swz64(r, ca));
            }
            // ---- B fragments (warp covers 32 n-cols) ----
            if (!TRANSB) {
                const int rb = (lane & 7) + ((lane >> 4) << 3);
                const int cb = 2 * st + ((lane >> 3) & 1);
#pragma unroll
                for (int p = 0; p < 2; p++) {
                    uint32_t tmp[4];
                    int r = wn * 32 + p * 16 + rb;
                    ldsm4(tmp, s0 + A_T + swz64(r, cb));
                    bh[2 * p][0] = tmp[0]; bh[2 * p][1] = tmp[1];
                    bh[2 * p + 1][0] = tmp[2]; bh[2 * p + 1][1] = tmp[3];
                    ldsm4(tmp, s0 + A_T + B_T + swz64(r, cb));
                    bl[2 * p][0] = tmp[0]; bl[2 * p][1] = tmp[1];
                    bl[2 * p + 1][0] = tmp[2]; bl[2 * p + 1][1] = tmp[3];
                }
            } else {
                const int kr = st * 16 + ((lane >> 3) & 1) * 8 + (lane & 7);
                const int cbase = wn * 4 + (lane >> 4);
#pragma unroll
                for (int p = 0; p < 2; p++) {
                    uint32_t tmp[4];
                    ldsm4t(tmp, s0 + A_T + swzT(kr, cbase + p * 2));
                    bh[2 * p][0] = tmp[0]; bh[2 * p][1] = tmp[1];
                    bh[2 * p + 1][0] = tmp[2]; bh[2 * p + 1][1] = tmp[3];
                    ldsm4t(tmp, s0 + A_T + B_T + swzT(kr, cbase + p * 2));
                    bl[2 * p][0] = tmp[0]; bl[2 * p][1] = tmp[1];
                    bl[2 * p + 1][0] = tmp[2]; bl[2 * p + 1][1] = tmp[3];
                }
            }
#pragma unroll
            for (int mf = 0; mf < 4; mf++)
#pragma unroll
                for (int nf = 0; nf < 4; nf++) mma16816(acc[mf][nf], ah[mf], bh[nf]);
#pragma unroll
            for (int mf = 0; mf < 4; mf++)
#pragma unroll
                for (int nf = 0; nf < 4; nf++) mma16816(acc[mf][nf], ah[mf], bl[nf]);
        }
    }

    // ---- epilogue ----
    const int qr = lane >> 2;
    const int qc = (lane & 3) * 2;
#pragma unroll
    for (int mf = 0; mf < 4; mf++) {
#pragma unroll
        for (int nf = 0; nf < 4; nf++) {
            size_t r0 = rowA0 + wm * 64 + mf * 16 + qr;
            int c0 = (int)rowB0 + wn * 32 + nf * 8 + qc;
            float v0 = acc[mf][nf][0] * alpha, v1 = acc[mf][nf][1] * alpha;
            float v2 = acc[mf][nf][2] * alpha, v3 = acc[mf][nf][3] * alpha;
            if (MODE == 0) {
                float* base = Cf + (size_t)bz * sC;
                *(float2*)(base + r0 * N + c0)       = make_float2(v0, v1);
                *(float2*)(base + (r0 + 8) * N + c0) = make_float2(v2, v3);
            } else if (MODE == 1) {
                __half h0, l0, h1, l1, h2, l2, h3, l3;
                split1h(v0, h0, l0); split1h(v1, h1, l1);
                split1h(v2, h2, l2); split1h(v3, h3, l3);
                size_t o1 = (size_t)bz * sC + r0 * N + c0;
                size_t o2 = (size_t)bz * sC + (r0 + 8) * N + c0;
                *(__half2*)(Chi + o1) = __halves2half2(h0, h1);
                *(__half2*)(Clo + o1) = __halves2half2(l0, l1);
                *(__half2*)(Chi + o2) = __halves2half2(h2, h3);
                *(__half2*)(Clo + o2) = __halves2half2(l2, l3);
            } else {  // MODE 2: plain fp16
                size_t o1 = (size_t)bz * sC + r0 * N + c0;
                size_t o2 = (size_t)bz * sC + (r0 + 8) * N + c0;
                *(__half2*)(Chi + o1) = __halves2half2(__float2half_rn(v0), __float2half_rn(v1));
                *(__half2*)(Chi + o2) = __halves2half2(__float2half_rn(v2), __float2half_rn(v3));
            }
        }
    }
}

// ---------------- convert fp32 -> fp16 (plain) -----------------------------
__global__ __launch_bounds__(256) void conv_kernel(
    const float* __restrict__ X, __half* __restrict__ H, int n4)
{
    int i = blockIdx.x * blockDim.x + threadIdx.x;
    if (i >= n4) return;
    float4 v = ((const float4*)X)[i];
    __half2 hu[2] = { __halves2half2(__float2half_rn(v.x), __float2half_rn(v.y)),
                      __halves2half2(__float2half_rn(v.z), __float2half_rn(v.w)) };
    ((uint2*)H)[i] = *(uint2*)hu;
}

// ---------------- split the 4 weight mats (blockIdx.z selects) -------------
__global__ __launch_bounds__(256) void splitW_kernel(
    const float* __restrict__ W0, const float* __restrict__ W1,
    const float* __restrict__ W2, const float* __restrict__ W3,
    __half* __restrict__ Hbase, __half* __restrict__ Lbase, int n4)
{
    int i = blockIdx.x * blockDim.x + threadIdx.x;
    if (i >= n4) return;
    int z = blockIdx.z;
    const float* X = (z == 0) ? W0 : (z == 1) ? W1 : (z == 2) ? W2 : W3;
    __half* H = Hbase + (size_t)z * ED * ED;
    __half* L = Lbase + (size_t)z * ED * ED;
    float4 v = ((const float4*)X)[i];
    __half h0, l0, h1, l1, h2, l2, h3, l3;
    split1h(v.x, h0, l0); split1h(v.y, h1, l1);
    split1h(v.z, h2, l2); split1h(v.w, h3, l3);
    __half2 hu[2] = { __halves2half2(h0, h1), __halves2half2(h2, h3) };
    __half2 lu[2] = { __halves2half2(l0, l1), __halves2half2(l2, l3) };
    ((uint2*)H)[i] = *(uint2*)hu;
    ((uint2*)L)[i] = *(uint2*)lu;
}

// ---------------- softmax: fp32 S row -> plain fp16 P ----------------------
__global__ __launch_bounds__(256) void softmax_row(
    const float* __restrict__ Sm, __half* __restrict__ Ph)
{
    const size_t rb = (size_t)blockIdx.x * SEQ;
    const float* p = Sm + rb;
    const int tid = threadIdx.x;
    __shared__ float red[8];

    float4 v[4];
    float m = -1e30f;
#pragma unroll
    for (int i = 0; i < 4; i++) {
        v[i] = *(const float4*)(p + (size_t)(i * 256 + tid) * 4);
        m = fmaxf(m, fmaxf(fmaxf(v[i].x, v[i].y), fmaxf(v[i].z, v[i].w)));
    }
#pragma unroll
    for (int o = 16; o; o >>= 1) m = fmaxf(m, __shfl_xor_sync(0xFFFFFFFFu, m, o));
    if ((tid & 31) == 0) red[tid >> 5] = m;
    __syncthreads();
    m = red[0];
#pragma unroll
    for (int w = 1; w < 8; w++) m = fmaxf(m, red[w]);
    __syncthreads();

    float s = 0.0f;
#pragma unroll
    for (int i = 0; i < 4; i++) {
        v[i].x = __expf(v[i].x - m); v[i].y = __expf(v[i].y - m);
        v[i].z = __expf(v[i].z - m); v[i].w = __expf(v[i].w - m);
        s += v[i].x + v[i].y + v[i].z + v[i].w;
    }
#pragma unroll
    for (int o = 16; o; o >>= 1) s += __shfl_xor_sync(0xFFFFFFFFu, s, o);
    if ((tid & 31) == 0) red[tid >> 5] = s;
    __syncthreads();
    s = red[0];
#pragma unroll
    for (int w = 1; w < 8; w++) s += red[w];
    const float r = 1.0f / s;

#pragma unroll
    for (int i = 0; i < 4; i++) {
        __half h0 = __float2half_rn(v[i].x * r);
        __half h1 = __float2half_rn(v[i].y * r);
        __half h2 = __float2half_rn(v[i].z * r);
        __half h3 = __float2half_rn(v[i].w * r);
        size_t idx = rb + (size_t)(i * 256 + tid) * 4;
        __half2 hu[2] = { __halves2half2(h0, h1), __halves2half2(h2, h3) };
        *(uint2*)(Ph + idx) = *(uint2*)hu;
    }
}

// ---------------------------------------------------------------------------
extern "C" void kernel_launch(void* const* d_in, const int* in_sizes, int n_in,
                              void* d_out, int out_size)
{
    const float* x  = (const float*)d_in[0];
    float* out = (float*)d_out;

    __half *xh, *Whi, *Wlo, *Qp, *Khi, *Klo, *Vhi, *Vlo, *Op, *Phi;
    float* S;
    cudaGetSymbolAddress((void**)&xh,  g_xh);
    cudaGetSymbolAddress((void**)&Whi, g_Whi); cudaGetSymbolAddress((void**)&Wlo, g_Wlo);
    cudaGetSymbolAddress((void**)&Qp,  g_Qp);
    cudaGetSymbolAddress((void**)&Khi, g_Khi); cudaGetSymbolAddress((void**)&Klo, g_Klo);
    cudaGetSymbolAddress((void**)&Vhi, g_Vhi); cudaGetSymbolAddress((void**)&Vlo, g_Vlo);
    cudaGetSymbolAddress((void**)&Op,  g_Op);
    cudaGetSymbolAddress((void**)&Phi, g_Phi);
    cudaGetSymbolAddress((void**)&S,   g_S);

    cudaFuncSetAttribute(gemm_fp16x2<0,0>, cudaFuncAttributeMaxDynamicSharedMemorySize, GSMEM);
    cudaFuncSetAttribute(gemm_fp16x2<1,0>, cudaFuncAttributeMaxDynamicSharedMemorySize, GSMEM);
    cudaFuncSetAttribute(gemm_fp16x2<2,0>, cudaFuncAttributeMaxDynamicSharedMemorySize, GSMEM);
    cudaFuncSetAttribute(gemm_fp16x2<2,1>, cudaFuncAttributeMaxDynamicSharedMemorySize, GSMEM);

    const size_t WSZ = (size_t)ED * ED;
    const size_t sQKV = (size_t)SEQ * ED;
    const size_t sS   = (size_t)SEQ * SEQ;

    // 1) convert x to fp16; split weights hi/lo
    {
        int n4 = (MTOT * ED) / 4;
        conv_kernel<<<(n4 + 255) / 256, 256>>>(x, xh, n4);
        int w4 = (int)(WSZ / 4);
        dim3 g((w4 + 255) / 256, 1, 4);
        splitW_kernel<<<g, 256>>>((const float*)d_in[1], (const float*)d_in[2],
                                  (const float*)d_in[3], (const float*)d_in[4],
                                  Whi, Wlo, w4);
    }

    // 2) projections (M=8192, N=1024, K=1024), 2-pass (A=xh, B=W hi+lo)
    {
        dim3 grid(ED / BN, MTOT / BM, 1);
        gemm_fp16x2<2,0><<<grid, 256, GSMEM>>>(xh, Whi + 0 * WSZ, Wlo + 0 * WSZ,
            nullptr, Qp, nullptr, ED, ED, 1.0f, 0, 0, 0);
        gemm_fp16x2<1,0><<<grid, 256, GSMEM>>>(xh, Whi + 1 * WSZ, Wlo + 1 * WSZ,
            nullptr, Khi, Klo, ED, ED, 1.0f, 0, 0, 0);
        gemm_fp16x2<1,0><<<grid, 256, GSMEM>>>(xh, Whi + 2 * WSZ, Wlo + 2 * WSZ,
            nullptr, Vhi, Vlo, ED, ED, 1.0f, 0, 0, 0);
    }

    // 3) scores S = Q K^T / 32 (batched; 2-pass: Qp*Khi + Qp*Klo)
    {
        dim3 grid(SEQ / BN, SEQ / BM, NB);
        gemm_fp16x2<0,0><<<grid, 256, GSMEM>>>(Qp, Khi, Klo,
            S, nullptr, nullptr, SEQ, ED, 0.03125f, sQKV, sQKV, sS);
    }

    // 4) softmax -> plain fp16 P
    softmax_row<<<NB * SEQ, 256>>>(S, Phi);

    // 5) O = P V (batched; 2-pass: P*Vhi + P*Vlo; V natural layout -> TRANSB)
    {
        dim3 grid(ED / BN, SEQ / BM, NB);
        gemm_fp16x2<2,1><<<grid, 256, GSMEM>>>(Phi, Vhi, Vlo,
            nullptr, Op, nullptr, ED, SEQ, 1.0f, sS, sQKV, sQKV);
    }

    // 6) out = O Wo^T (M=8192, N=1024, K=1024), 2-pass, fp32 result
    {
        dim3 grid(ED / BN, MTOT / BM, 1);
        gemm_fp16x2<0,0><<<grid, 256, GSMEM>>>(Op, Whi + 3 * WSZ, Wlo + 3 * WSZ,
            out, nullptr, nullptr, ED, ED, 1.0f, 0, 0, 0);
    }
}

// round 11
// speedup vs baseline: 1.4667x; 1.4667x over previous
#include <cuda_runtime.h>
#include <cuda_fp16.h>
#include <math.h>
#include <stdint.h>

#define ED 1024
#define NB 2
#define SEQ 4096
#define MTOT (NB * SEQ)

// ---------------- scratch (static device globals; no allocs allowed) -------
__device__ __half g_xh [(size_t)MTOT * ED];            // x rounded to fp16
__device__ __half g_Whi[4][(size_t)ED * ED];           // q,k,v,o weight hi
__device__ __half g_Wlo[4][(size_t)ED * ED];           // q,k,v,o weight lo
__device__ __half g_Qp [(size_t)MTOT * ED];            // plain fp16
__device__ __half g_Kp [(size_t)MTOT * ED];            // plain fp16
__device__ __half g_Vp [(size_t)MTOT * ED];            // plain fp16, [b][s][d]
__device__ __half g_Op [(size_t)MTOT * ED];            // plain fp16
__device__ float  g_S  [(size_t)NB * SEQ * SEQ];
__device__ __half g_Phi[(size_t)NB * SEQ * SEQ];

// ---------------- PTX helpers ---------------------------------------------
__device__ __forceinline__ uint32_t smem_u32(const void* p) {
    uint32_t a;
    asm("{ .reg .u64 t; cvta.to.shared.u64 t, %1; cvt.u32.u64 %0, t; }" : "=r"(a) : "l"(p));
    return a;
}
__device__ __forceinline__ void cp16(uint32_t dst, const void* src) {
    asm volatile("cp.async.cg.shared.global [%0], [%1], 16;" :: "r"(dst), "l"(src));
}
#define CP_COMMIT() asm volatile("cp.async.commit_group;" ::: "memory")

__device__ __forceinline__ void ldsm4(uint32_t* r, uint32_t addr) {
    asm volatile("ldmatrix.sync.aligned.m8n8.x4.shared.b16 {%0,%1,%2,%3}, [%4];"
                 : "=r"(r[0]), "=r"(r[1]), "=r"(r[2]), "=r"(r[3]) : "r"(addr));
}
__device__ __forceinline__ void ldsm4t(uint32_t* r, uint32_t addr) {
    asm volatile("ldmatrix.sync.aligned.m8n8.x4.trans.shared.b16 {%0,%1,%2,%3}, [%4];"
                 : "=r"(r[0]), "=r"(r[1]), "=r"(r[2]), "=r"(r[3]) : "r"(addr));
}
__device__ __forceinline__ void mma16816(float* c, const uint32_t* a, const uint32_t* b) {
    asm volatile(
        "mma.sync.aligned.m16n8k16.row.col.f32.f16.f16.f32 "
        "{%0,%1,%2,%3}, {%4,%5,%6,%7}, {%8,%9}, {%0,%1,%2,%3};\n"
        : "+f"(c[0]), "+f"(c[1]), "+f"(c[2]), "+f"(c[3])
        : "r"(a[0]), "r"(a[1]), "r"(a[2]), "r"(a[3]), "r"(b[0]), "r"(b[1]));
}
__device__ __forceinline__ void split1h(float v, __half& h, __half& l) {
    h = __float2half_rn(v);
    l = __float2half_rn(v - __half2float(h));
}

// ---------------- GEMM config ----------------------------------------------
// Block 128(M) x 128(N) x 64(K). 8 warps (2M x 4N), warp tile 64x32.
// 2-stage pipeline, 2 CTAs/SM, <=128 regs.  A plain fp16.
// BLO=1: B split hi/lo (2 MMA passes). BLO=0: B plain (1 pass).
// TRANSB=0: B is [N,K] k-major. TRANSB=1: B is [K,N] (V natural layout).
// MODE 0: fp32*alpha   MODE 2: plain fp16 (Chi)
#define BM 128
#define BN 128
#define BK 64
#define A_T  ((uint32_t)(BM * BK * 2))          // 16 KB
#define B_T  ((uint32_t)(BN * BK * 2))          // 16 KB per half-tile
#define STGB(BLO)  (A_T + ((BLO) ? 2u : 1u) * B_T)
#define GSMEM(BLO) (2u * STGB(BLO))

// 128B rows (64 halves), 16B chunk c in 0..7
__device__ __forceinline__ uint32_t swz128(int r, int c) {
    return (uint32_t)(r * 128 + ((c ^ (r & 7)) << 4));
}
// 256B rows (128 halves), 16B chunk c in 0..15
__device__ __forceinline__ uint32_t swzT(int r, int c) {
    return (uint32_t)(r * 256 + ((c ^ (r & 7)) << 4));
}

template <int TRANSB, int BLO>
__device__ __forceinline__ void load_stage_g(
    uint32_t s0, const __half* __restrict__ Ap,
    const __half* __restrict__ Bhi, const __half* __restrict__ Blo,
    size_t rowA0, size_t rowB0, int N, int K, int k0, int tid)
{
#pragma unroll
    for (int i = 0; i < 4; i++) {               // A: 128 rows x 8 chunks = 1024
        int idx = tid + i * 256;
        int r = idx >> 3, c = idx & 7;
        cp16(s0 + swz128(r, c), Ap + (rowA0 + r) * (size_t)K + k0 + c * 8);
    }
#pragma unroll
    for (int h = 0; h < (BLO ? 2 : 1); h++) {
        const __half* g = h ? Blo : Bhi;
        uint32_t d0 = s0 + A_T + h * B_T;
        if (!TRANSB) {
#pragma unroll
            for (int i = 0; i < 4; i++) {       // 128 rows x 8 chunks = 1024
                int idx = tid + i * 256;
                int r = idx >> 3, c = idx & 7;
                cp16(d0 + swz128(r, c), g + (rowB0 + r) * (size_t)K + k0 + c * 8);
            }
        } else {
#pragma unroll
            for (int i = 0; i < 4; i++) {       // 64 rows x 16 chunks = 1024
                int idx = tid + i * 256;
                int r = idx >> 4, c = idx & 15;
                cp16(d0 + swzT(r, c), g + (size_t)(k0 + r) * N + rowB0 + c * 8);
            }
        }
    }
    CP_COMMIT();
}

template <int MODE, int TRANSB, int BLO>
__global__ __launch_bounds__(256, 2) void gemm_fp16(
    const __half* __restrict__ Ap,
    const __half* __restrict__ Bhi, const __half* __restrict__ Blo,
    float* __restrict__ Cf, __half* __restrict__ Chi,
    int N, int K, float alpha, size_t sA, size_t sB, size_t sC)
{
    extern __shared__ char smem[];
    const uint32_t sb = smem_u32(smem);
    const uint32_t STG = STGB(BLO);
    const int tid = threadIdx.x, lane = tid & 31, wid = tid >> 5;
    const int wm = wid >> 2, wn = wid & 3;
    const int bz = blockIdx.z;
    Ap  += (size_t)bz * sA;
    Bhi += (size_t)bz * sB; if (BLO) Blo += (size_t)bz * sB;
    const size_t rowA0 = (size_t)blockIdx.y * BM;
    const size_t rowB0 = (size_t)blockIdx.x * BN;

    float acc[4][4][4];
#pragma unroll
    for (int a = 0; a < 4; a++)
#pragma unroll
        for (int b = 0; b < 4; b++)
#pragma unroll
            for (int k = 0; k < 4; k++) acc[a][b][k] = 0.0f;

    const int T = K / BK;
    load_stage_g<TRANSB, BLO>(sb, Ap, Bhi, Blo, rowA0, rowB0, N, K, 0, tid);
    load_stage_g<TRANSB, BLO>(sb + STG, Ap, Bhi, Blo, rowA0, rowB0, N, K, BK, tid);

    for (int t = 0; t < T; t++) {
        if (t + 1 < T)
            asm volatile("cp.async.wait_group 1;" ::: "memory");
        else
            asm volatile("cp.async.wait_group 0;" ::: "memory");
        __syncthreads();

        const uint32_t s0 = sb + (uint32_t)(t & 1) * STG;
#pragma unroll
        for (int st = 0; st < 4; st++) {
            uint32_t ah[4][4], bh[4][2], bl[4][2];
            // ---- A fragments ----
            const int ra = lane & 15;
            const int ca = 2 * st + (lane >> 4);
#pragma unroll
            for (int mf = 0; mf < 4; mf++) {
                int r = wm * 64 + mf * 16 + ra;
                ldsm4(ah[mf], s0 + swz128(r, ca));
            }
            // ---- B fragments (warp covers 32 n-cols) ----
            if (!TRANSB) {
                const int rb = (lane & 7) + ((lane >> 4) << 3);
                const int cb = 2 * st + ((lane >> 3) & 1);
#pragma unroll
                for (int p = 0; p < 2; p++) {
                    uint32_t tmp[4];
                    int r = wn * 32 + p * 16 + rb;
                    ldsm4(tmp, s0 + A_T + swz128(r, cb));
                    bh[2 * p][0] = tmp[0]; bh[2 * p][1] = tmp[1];
                    bh[2 * p + 1][0] = tmp[2]; bh[2 * p + 1][1] = tmp[3];
                    if (BLO) {
                        ldsm4(tmp, s0 + A_T + B_T + swz128(r, cb));
                        bl[2 * p][0] = tmp[0]; bl[2 * p][1] = tmp[1];
                        bl[2 * p + 1][0] = tmp[2]; bl[2 * p + 1][1] = tmp[3];
                    }
                }
            } else {
                const int kr = st * 16 + ((lane >> 3) & 1) * 8 + (lane & 7);
                const int cbase = wn * 4 + (lane >> 4);
#pragma unroll
                for (int p = 0; p < 2; p++) {
                    uint32_t tmp[4];
                    ldsm4t(tmp, s0 + A_T + swzT(kr, cbase + p * 2));
                    bh[2 * p][0] = tmp[0]; bh[2 * p][1] = tmp[1];
                    bh[2 * p + 1][0] = tmp[2]; bh[2 * p + 1][1] = tmp[3];
                    if (BLO) {
                        ldsm4t(tmp, s0 + A_T + B_T + swzT(kr, cbase + p * 2));
                        bl[2 * p][0] = tmp[0]; bl[2 * p][1] = tmp[1];
                        bl[2 * p + 1][0] = tmp[2]; bl[2 * p + 1][1] = tmp[3];
                    }
                }
            }
#pragma unroll
            for (int mf = 0; mf < 4; mf++)
#pragma unroll
                for (int nf = 0; nf < 4; nf++) mma16816(acc[mf][nf], ah[mf], bh[nf]);
            if (BLO) {
#pragma unroll
                for (int mf = 0; mf < 4; mf++)
#pragma unroll
                    for (int nf = 0; nf < 4; nf++) mma16816(acc[mf][nf], ah[mf], bl[nf]);
            }
        }
        __syncthreads();
        if (t + 2 < T)
            load_stage_g<TRANSB, BLO>(sb + (uint32_t)(t & 1) * STG,
                                      Ap, Bhi, Blo, rowA0, rowB0, N, K,
                                      (t + 2) * BK, tid);
    }

    // ---- epilogue ----
    const int qr = lane >> 2;
    const int qc = (lane & 3) * 2;
#pragma unroll
    for (int mf = 0; mf < 4; mf++) {
#pragma unroll
        for (int nf = 0; nf < 4; nf++) {
            size_t r0 = rowA0 + wm * 64 + mf * 16 + qr;
            int c0 = (int)rowB0 + wn * 32 + nf * 8 + qc;
            float v0 = acc[mf][nf][0] * alpha, v1 = acc[mf][nf][1] * alpha;
            float v2 = acc[mf][nf][2] * alpha, v3 = acc[mf][nf][3] * alpha;
            if (MODE == 0) {
                float* base = Cf + (size_t)bz * sC;
                *(float2*)(base + r0 * N + c0)       = make_float2(v0, v1);
                *(float2*)(base + (r0 + 8) * N + c0) = make_float2(v2, v3);
            } else {  // MODE 2: plain fp16
                size_t o1 = (size_t)bz * sC + r0 * N + c0;
                size_t o2 = (size_t)bz * sC + (r0 + 8) * N + c0;
                *(__half2*)(Chi + o1) = __halves2half2(__float2half_rn(v0), __float2half_rn(v1));
                *(__half2*)(Chi + o2) = __halves2half2(__float2half_rn(v2), __float2half_rn(v3));
            }
        }
    }
}

// ---------------- convert fp32 -> fp16 (plain) -----------------------------
__global__ __launch_bounds__(256) void conv_kernel(
    const float* __restrict__ X, __half* __restrict__ H, int n4)
{
    int i = blockIdx.x * blockDim.x + threadIdx.x;
    if (i >= n4) return;
    float4 v = ((const float4*)X)[i];
    __half2 hu[2] = { __halves2half2(__float2half_rn(v.x), __float2half_rn(v.y)),
                      __halves2half2(__float2half_rn(v.z), __float2half_rn(v.w)) };
    ((uint2*)H)[i] = *(uint2*)hu;
}

// ---------------- split the 4 weight mats (blockIdx.z selects) -------------
__global__ __launch_bounds__(256) void splitW_kernel(
    const float* __restrict__ W0, const float* __restrict__ W1,
    const float* __restrict__ W2, const float* __restrict__ W3,
    __half* __restrict__ Hbase, __half* __restrict__ Lbase, int n4)
{
    int i = blockIdx.x * blockDim.x + threadIdx.x;
    if (i >= n4) return;
    int z = blockIdx.z;
    const float* X = (z == 0) ? W0 : (z == 1) ? W1 : (z == 2) ? W2 : W3;
    __half* H = Hbase + (size_t)z * ED * ED;
    __half* L = Lbase + (size_t)z * ED * ED;
    float4 v = ((const float4*)X)[i];
    __half h0, l0, h1, l1, h2, l2, h3, l3;
    split1h(v.x, h0, l0); split1h(v.y, h1, l1);
    split1h(v.z, h2, l2); split1h(v.w, h3, l3);
    __half2 hu[2] = { __halves2half2(h0, h1), __halves2half2(h2, h3) };
    __half2 lu[2] = { __halves2half2(l0, l1), __halves2half2(l2, l3) };
    ((uint2*)H)[i] = *(uint2*)hu;
    ((uint2*)L)[i] = *(uint2*)lu;
}

// ---------------- softmax: fp32 S row -> plain fp16 P ----------------------
__global__ __launch_bounds__(256) void softmax_row(
    const float* __restrict__ Sm, __half* __restrict__ Ph)
{
    const size_t rb = (size_t)blockIdx.x * SEQ;
    const float* p = Sm + rb;
    const int tid = threadIdx.x;
    __shared__ float red[8];

    float4 v[4];
    float m = -1e30f;
#pragma unroll
    for (int i = 0; i < 4; i++) {
        v[i] = *(const float4*)(p + (size_t)(i * 256 + tid) * 4);
        m = fmaxf(m, fmaxf(fmaxf(v[i].x, v[i].y), fmaxf(v[i].z, v[i].w)));
    }
#pragma unroll
    for (int o = 16; o; o >>= 1) m = fmaxf(m, __shfl_xor_sync(0xFFFFFFFFu, m, o));
    if ((tid & 31) == 0) red[tid >> 5] = m;
    __syncthreads();
    m = red[0];
#pragma unroll
    for (int w = 1; w < 8; w++) m = fmaxf(m, red[w]);
    __syncthreads();

    float s = 0.0f;
#pragma unroll
    for (int i = 0; i < 4; i++) {
        v[i].x = __expf(v[i].x - m); v[i].y = __expf(v[i].y - m);
        v[i].z = __expf(v[i].z - m); v[i].w = __expf(v[i].w - m);
        s += v[i].x + v[i].y + v[i].z + v[i].w;
    }
#pragma unroll
    for (int o = 16; o; o >>= 1) s += __shfl_xor_sync(0xFFFFFFFFu, s, o);
    if ((tid & 31) == 0) red[tid >> 5] = s;
    __syncthreads();
    s = red[0];
#pragma unroll
    for (int w = 1; w < 8; w++) s += red[w];
    const float r = 1.0f / s;

#pragma unroll
    for (int i = 0; i < 4; i++) {
        __half h0 = __float2half_rn(v[i].x * r);
        __half h1 = __float2half_rn(v[i].y * r);
        __half h2 = __float2half_rn(v[i].z * r);
        __half h3 = __float2half_rn(v[i].w * r);
        size_t idx = rb + (size_t)(i * 256 + tid) * 4;
        __half2 hu[2] = { __halves2half2(h0, h1), __halves2half2(h2, h3) };
        *(uint2*)(Ph + idx) = *(uint2*)hu;
    }
}

// ---------------------------------------------------------------------------
extern "C" void kernel_launch(void* const* d_in, const int* in_sizes, int n_in,
                              void* d_out, int out_size)
{
    const float* x  = (const float*)d_in[0];
    float* out = (float*)d_out;

    __half *xh, *Whi, *Wlo, *Qp, *Kp, *Vp, *Op, *Phi;
    float* S;
    cudaGetSymbolAddress((void**)&xh,  g_xh);
    cudaGetSymbolAddress((void**)&Whi, g_Whi); cudaGetSymbolAddress((void**)&Wlo, g_Wlo);
    cudaGetSymbolAddress((void**)&Qp,  g_Qp);  cudaGetSymbolAddress((void**)&Kp,  g_Kp);
    cudaGetSymbolAddress((void**)&Vp,  g_Vp);  cudaGetSymbolAddress((void**)&Op,  g_Op);
    cudaGetSymbolAddress((void**)&Phi, g_Phi);
    cudaGetSymbolAddress((void**)&S,   g_S);

    cudaFuncSetAttribute(gemm_fp16<2,0,1>, cudaFuncAttributeMaxDynamicSharedMemorySize, GSMEM(1));
    cudaFuncSetAttribute(gemm_fp16<0,0,1>, cudaFuncAttributeMaxDynamicSharedMemorySize, GSMEM(1));
    cudaFuncSetAttribute(gemm_fp16<0,0,0>, cudaFuncAttributeMaxDynamicSharedMemorySize, GSMEM(0));
    cudaFuncSetAttribute(gemm_fp16<2,1,0>, cudaFuncAttributeMaxDynamicSharedMemorySize, GSMEM(0));

    const size_t WSZ = (size_t)ED * ED;
    const size_t sQKV = (size_t)SEQ * ED;
    const size_t sS   = (size_t)SEQ * SEQ;

    // 1) convert x to fp16; split weights hi/lo
    {
        int n4 = (MTOT * ED) / 4;
        conv_kernel<<<(n4 + 255) / 256, 256>>>(x, xh, n4);
        int w4 = (int)(WSZ / 4);
        dim3 g((w4 + 255) / 256, 1, 4);
        splitW_kernel<<<g, 256>>>((const float*)d_in[1], (const float*)d_in[2],
                                  (const float*)d_in[3], (const float*)d_in[4],
                                  Whi, Wlo, w4);
    }

    // 2) projections (M=8192, N=1024, K=1024), 2-pass in W; plain fp16 out
    {
        dim3 grid(ED / BN, MTOT / BM, 1);
        gemm_fp16<2,0,1><<<grid, 256, GSMEM(1)>>>(xh, Whi + 0 * WSZ, Wlo + 0 * WSZ,
            nullptr, Qp, ED, ED, 1.0f, 0, 0, 0);
        gemm_fp16<2,0,1><<<grid, 256, GSMEM(1)>>>(xh, Whi + 1 * WSZ, Wlo + 1 * WSZ,
            nullptr, Kp, ED, ED, 1.0f, 0, 0, 0);
        gemm_fp16<2,0,1><<<grid, 256, GSMEM(1)>>>(xh, Whi + 2 * WSZ, Wlo + 2 * WSZ,
            nullptr, Vp, ED, ED, 1.0f, 0, 0, 0);
    }

    // 3) scores S = Qp Kp^T / 32 (batched; 1-pass)
    {
        dim3 grid(SEQ / BN, SEQ / BM, NB);
        gemm_fp16<0,0,0><<<grid, 256, GSMEM(0)>>>(Qp, Kp, nullptr,
            S, nullptr, SEQ, ED, 0.03125f, sQKV, sQKV, sS);
    }

    // 4) softmax -> plain fp16 P
    softmax_row<<<NB * SEQ, 256>>>(S, Phi);

    // 5) O = P Vp (batched; 1-pass; V natural layout -> TRANSB)
    {
        dim3 grid(ED / BN, SEQ / BM, NB);
        gemm_fp16<2,1,0><<<grid, 256, GSMEM(0)>>>(Phi, Vp, nullptr,
            nullptr, Op, ED, SEQ, 1.0f, sS, sQKV, sQKV);
    }

    // 6) out = O Wo^T (M=8192, N=1024, K=1024), 2-pass in W, fp32 result
    {
        dim3 grid(ED / BN, MTOT / BM, 1);
        gemm_fp16<0,0,1><<<grid, 256, GSMEM(1)>>>(Op, Whi + 3 * WSZ, Wlo + 3 * WSZ,
            out, nullptr, ED, ED, 1.0f, 0, 0, 0);
    }
}

// round 12
// speedup vs baseline: 1.8921x; 1.2901x over previous
#include <cuda_runtime.h>
#include <cuda_fp16.h>
#include <math.h>
#include <stdint.h>

#define ED 1024
#define NB 2
#define SEQ 4096
#define MTOT (NB * SEQ)

// ---------------- scratch (static device globals; no allocs allowed) -------
__device__ __half g_xh [(size_t)MTOT * ED];            // x rounded to fp16
__device__ __half g_Wh [4][(size_t)ED * ED];           // q,k,v,o weights fp16
__device__ __half g_QKV[3][(size_t)MTOT * ED];         // Q, K, V plain fp16
__device__ __half g_Op [(size_t)MTOT * ED];            // O plain fp16
__device__ float  g_S  [(size_t)NB * SEQ * SEQ];
__device__ __half g_Phi[(size_t)NB * SEQ * SEQ];

// ---------------- PTX helpers ---------------------------------------------
__device__ __forceinline__ uint32_t smem_u32(const void* p) {
    uint32_t a;
    asm("{ .reg .u64 t; cvta.to.shared.u64 t, %1; cvt.u32.u64 %0, t; }" : "=r"(a) : "l"(p));
    return a;
}
__device__ __forceinline__ void cp16(uint32_t dst, const void* src) {
    asm volatile("cp.async.cg.shared.global [%0], [%1], 16;" :: "r"(dst), "l"(src));
}
#define CP_COMMIT() asm volatile("cp.async.commit_group;" ::: "memory")

__device__ __forceinline__ void ldsm4(uint32_t* r, uint32_t addr) {
    asm volatile("ldmatrix.sync.aligned.m8n8.x4.shared.b16 {%0,%1,%2,%3}, [%4];"
                 : "=r"(r[0]), "=r"(r[1]), "=r"(r[2]), "=r"(r[3]) : "r"(addr));
}
__device__ __forceinline__ void ldsm4t(uint32_t* r, uint32_t addr) {
    asm volatile("ldmatrix.sync.aligned.m8n8.x4.trans.shared.b16 {%0,%1,%2,%3}, [%4];"
                 : "=r"(r[0]), "=r"(r[1]), "=r"(r[2]), "=r"(r[3]) : "r"(addr));
}
__device__ __forceinline__ void mma16816(float* c, const uint32_t* a, const uint32_t* b) {
    asm volatile(
        "mma.sync.aligned.m16n8k16.row.col.f32.f16.f16.f32 "
        "{%0,%1,%2,%3}, {%4,%5,%6,%7}, {%8,%9}, {%0,%1,%2,%3};\n"
        : "+f"(c[0]), "+f"(c[1]), "+f"(c[2]), "+f"(c[3])
        : "r"(a[0]), "r"(a[1]), "r"(a[2]), "r"(a[3]), "r"(b[0]), "r"(b[1]));
}

// ---------------- GEMM config ----------------------------------------------
// Block 128(M) x 128(N) x 64(K). 8 warps (2M x 4N), warp tile 64x32.
// 2-stage pipeline, 2 CTAs/SM, <=128 regs. A and B plain fp16 (1 pass).
// TRANSB=0: B is [N,K] k-major. TRANSB=1: B is [K,N] (V natural layout).
// MODE 0: fp32*alpha   MODE 2: plain fp16 (Chi)
// MODE 3: fused-QKV routing: output matrix = c0>>10, local col = c0&1023
#define BM 128
#define BN 128
#define BK 64
#define A_T  ((uint32_t)(BM * BK * 2))          // 16 KB
#define B_T  ((uint32_t)(BN * BK * 2))          // 16 KB
#define STG_B (A_T + B_T)                       // 32 KB per stage
#define GSMEM (2u * STG_B)                      // 64 KB -> 2 CTAs/SM

// 128B rows (64 halves), 16B chunk c in 0..7
__device__ __forceinline__ uint32_t swz128(int r, int c) {
    return (uint32_t)(r * 128 + ((c ^ (r & 7)) << 4));
}
// 256B rows (128 halves), 16B chunk c in 0..15
__device__ __forceinline__ uint32_t swzT(int r, int c) {
    return (uint32_t)(r * 256 + ((c ^ (r & 7)) << 4));
}

template <int TRANSB>
__device__ __forceinline__ void load_stage_g(
    uint32_t s0, const __half* __restrict__ Ap, const __half* __restrict__ Bp,
    size_t rowA0, size_t rowB0, int N, int K, int k0, int tid)
{
#pragma unroll
    for (int i = 0; i < 4; i++) {               // A: 128 rows x 8 chunks = 1024
        int idx = tid + i * 256;
        int r = idx >> 3, c = idx & 7;
        cp16(s0 + swz128(r, c), Ap + (rowA0 + r) * (size_t)K + k0 + c * 8);
    }
    if (!TRANSB) {
#pragma unroll
        for (int i = 0; i < 4; i++) {           // 128 rows x 8 chunks = 1024
            int idx = tid + i * 256;
            int r = idx >> 3, c = idx & 7;
            cp16(s0 + A_T + swz128(r, c), Bp + (rowB0 + r) * (size_t)K + k0 + c * 8);
        }
    } else {
#pragma unroll
        for (int i = 0; i < 4; i++) {           // 64 rows x 16 chunks = 1024
            int idx = tid + i * 256;
            int r = idx >> 4, c = idx & 15;
            cp16(s0 + A_T + swzT(r, c), Bp + (size_t)(k0 + r) * N + rowB0 + c * 8);
        }
    }
    CP_COMMIT();
}

template <int MODE, int TRANSB>
__global__ __launch_bounds__(256, 2) void gemm_fp16(
    const __half* __restrict__ Ap, const __half* __restrict__ Bp,
    float* __restrict__ Cf, __half* __restrict__ Chi,
    int N, int K, float alpha, size_t sA, size_t sB, size_t sC)
{
    extern __shared__ char smem[];
    const uint32_t sb = smem_u32(smem);
    const int tid = threadIdx.x, lane = tid & 31, wid = tid >> 5;
    const int wm = wid >> 2, wn = wid & 3;
    const int bz = blockIdx.z;
    Ap += (size_t)bz * sA;
    Bp += (size_t)bz * sB;
    const size_t rowA0 = (size_t)blockIdx.y * BM;
    const size_t rowB0 = (size_t)blockIdx.x * BN;

    float acc[4][4][4];
#pragma unroll
    for (int a = 0; a < 4; a++)
#pragma unroll
        for (int b = 0; b < 4; b++)
#pragma unroll
            for (int k = 0; k < 4; k++) acc[a][b][k] = 0.0f;

    const int T = K / BK;
    load_stage_g<TRANSB>(sb, Ap, Bp, rowA0, rowB0, N, K, 0, tid);
    load_stage_g<TRANSB>(sb + STG_B, Ap, Bp, rowA0, rowB0, N, K, BK, tid);

    for (int t = 0; t < T; t++) {
        if (t + 1 < T)
            asm volatile("cp.async.wait_group 1;" ::: "memory");
        else
            asm volatile("cp.async.wait_group 0;" ::: "memory");
        __syncthreads();

        const uint32_t s0 = sb + (uint32_t)(t & 1) * STG_B;
#pragma unroll
        for (int st = 0; st < 4; st++) {
            uint32_t ah[4][4], bh[4][2];
            const int ra = lane & 15;
            const int ca = 2 * st + (lane >> 4);
#pragma unroll
            for (int mf = 0; mf < 4; mf++) {
                int r = wm * 64 + mf * 16 + ra;
                ldsm4(ah[mf], s0 + swz128(r, ca));
            }
            if (!TRANSB) {
                const int rb = (lane & 7) + ((lane >> 4) << 3);
                const int cb = 2 * st + ((lane >> 3) & 1);
#pragma unroll
                for (int p = 0; p < 2; p++) {
                    uint32_t tmp[4];
                    int r = wn * 32 + p * 16 + rb;
                    ldsm4(tmp, s0 + A_T + swz128(r, cb));
                    bh[2 * p][0] = tmp[0]; bh[2 * p][1] = tmp[1];
                    bh[2 * p + 1][0] = tmp[2]; bh[2 * p + 1][1] = tmp[3];
                }
            } else {
                const int kr = st * 16 + ((lane >> 3) & 1) * 8 + (lane & 7);
                const int cbase = wn * 4 + (lane >> 4);
#pragma unroll
                for (int p = 0; p < 2; p++) {
                    uint32_t tmp[4];
                    ldsm4t(tmp, s0 + A_T + swzT(kr, cbase + p * 2));
                    bh[2 * p][0] = tmp[0]; bh[2 * p][1] = tmp[1];
                    bh[2 * p + 1][0] = tmp[2]; bh[2 * p + 1][1] = tmp[3];
                }
            }
#pragma unroll
            for (int mf = 0; mf < 4; mf++)
#pragma unroll
                for (int nf = 0; nf < 4; nf++) mma16816(acc[mf][nf], ah[mf], bh[nf]);
        }
        __syncthreads();
        if (t + 2 < T)
            load_stage_g<TRANSB>(sb + (uint32_t)(t & 1) * STG_B,
                                 Ap, Bp, rowA0, rowB0, N, K, (t + 2) * BK, tid);
    }

    // ---- epilogue ----
    const int qr = lane >> 2;
    const int qc = (lane & 3) * 2;
#pragma unroll
    for (int mf = 0; mf < 4; mf++) {
#pragma unroll
        for (int nf = 0; nf < 4; nf++) {
            size_t r0 = rowA0 + wm * 64 + mf * 16 + qr;
            int c0 = (int)rowB0 + wn * 32 + nf * 8 + qc;
            float v0 = acc[mf][nf][0] * alpha, v1 = acc[mf][nf][1] * alpha;
            float v2 = acc[mf][nf][2] * alpha, v3 = acc[mf][nf][3] * alpha;
            if (MODE == 0) {
                float* base = Cf + (size_t)bz * sC;
                *(float2*)(base + r0 * N + c0)       = make_float2(v0, v1);
                *(float2*)(base + (r0 + 8) * N + c0) = make_float2(v2, v3);
            } else if (MODE == 2) {
                size_t o1 = (size_t)bz * sC + r0 * N + c0;
                size_t o2 = (size_t)bz * sC + (r0 + 8) * N + c0;
                *(__half2*)(Chi + o1) = __halves2half2(__float2half_rn(v0), __float2half_rn(v1));
                *(__half2*)(Chi + o2) = __halves2half2(__float2half_rn(v2), __float2half_rn(v3));
            } else {  // MODE 3: fused QKV — route to matrix c0>>10
                int mtx = c0 >> 10;
                int lc  = c0 & 1023;
                size_t base = (size_t)mtx * ((size_t)MTOT * ED);
                size_t o1 = base + r0 * ED + lc;
                size_t o2 = base + (r0 + 8) * ED + lc;
                *(__half2*)(Chi + o1) = __halves2half2(__float2half_rn(v0), __float2half_rn(v1));
                *(__half2*)(Chi + o2) = __halves2half2(__float2half_rn(v2), __float2half_rn(v3));
            }
        }
    }
}

// ---------------- convert fp32 -> fp16 (x and 4 weights via blockIdx.z) ----
__global__ __launch_bounds__(256) void conv_all_kernel(
    const float* __restrict__ X,
    const float* __restrict__ W0, const float* __restrict__ W1,
    const float* __restrict__ W2, const float* __restrict__ W3,
    __half* __restrict__ XH, __half* __restrict__ WH)
{
    int z = blockIdx.z;          // 0: x (8M elems), 1..4: weights (1M each)
    const float* src; __half* dst; int n4;
    if (z == 0) { src = X;  dst = XH; n4 = (MTOT * ED) / 4; }
    else {
        src = (z == 1) ? W0 : (z == 2) ? W1 : (z == 3) ? W2 : W3;
        dst = WH + (size_t)(z - 1) * ED * ED;
        n4 = (ED * ED) / 4;
    }
    for (int i = blockIdx.x * blockDim.x + threadIdx.x; i < n4;
         i += gridDim.x * blockDim.x) {
        float4 v = ((const float4*)src)[i];
        __half2 hu[2] = { __halves2half2(__float2half_rn(v.x), __float2half_rn(v.y)),
                          __halves2half2(__float2half_rn(v.z), __float2half_rn(v.w)) };
        ((uint2*)dst)[i] = *(uint2*)hu;
    }
}

// ---------------- softmax: fp32 S row -> plain fp16 P ----------------------
__global__ __launch_bounds__(256) void softmax_row(
    const float* __restrict__ Sm, __half* __restrict__ Ph)
{
    const size_t rb = (size_t)blockIdx.x * SEQ;
    const float* p = Sm + rb;
    const int tid = threadIdx.x;
    __shared__ float red[8];

    float4 v[4];
    float m = -1e30f;
#pragma unroll
    for (int i = 0; i < 4; i++) {
        v[i] = *(const float4*)(p + (size_t)(i * 256 + tid) * 4);
        m = fmaxf(m, fmaxf(fmaxf(v[i].x, v[i].y), fmaxf(v[i].z, v[i].w)));
    }
#pragma unroll
    for (int o = 16; o; o >>= 1) m = fmaxf(m, __shfl_xor_sync(0xFFFFFFFFu, m, o));
    if ((tid & 31) == 0) red[tid >> 5] = m;
    __syncthreads();
    m = red[0];
#pragma unroll
    for (int w = 1; w < 8; w++) m = fmaxf(m, red[w]);
    __syncthreads();

    float s = 0.0f;
#pragma unroll
    for (int i = 0; i < 4; i++) {
        v[i].x = __expf(v[i].x - m); v[i].y = __expf(v[i].y - m);
        v[i].z = __expf(v[i].z - m); v[i].w = __expf(v[i].w - m);
        s += v[i].x + v[i].y + v[i].z + v[i].w;
    }
#pragma unroll
    for (int o = 16; o; o >>= 1) s += __shfl_xor_sync(0xFFFFFFFFu, s, o);
    if ((tid & 31) == 0) red[tid >> 5] = s;
    __syncthreads();
    s = red[0];
#pragma unroll
    for (int w = 1; w < 8; w++) s += red[w];
    const float r = 1.0f / s;

#pragma unroll
    for (int i = 0; i < 4; i++) {
        __half h0 = __float2half_rn(v[i].x * r);
        __half h1 = __float2half_rn(v[i].y * r);
        __half h2 = __float2half_rn(v[i].z * r);
        __half h3 = __float2half_rn(v[i].w * r);
        size_t idx = rb + (size_t)(i * 256 + tid) * 4;
        __half2 hu[2] = { __halves2half2(h0, h1), __halves2half2(h2, h3) };
        *(uint2*)(Ph + idx) = *(uint2*)hu;
    }
}

// ---------------------------------------------------------------------------
extern "C" void kernel_launch(void* const* d_in, const int* in_sizes, int n_in,
                              void* d_out, int out_size)
{
    const float* x  = (const float*)d_in[0];
    float* out = (float*)d_out;

    __half *xh, *Wh, *QKV, *Op, *Phi;
    float* S;
    cudaGetSymbolAddress((void**)&xh,  g_xh);
    cudaGetSymbolAddress((void**)&Wh,  g_Wh);
    cudaGetSymbolAddress((void**)&QKV, g_QKV);
    cudaGetSymbolAddress((void**)&Op,  g_Op);
    cudaGetSymbolAddress((void**)&Phi, g_Phi);
    cudaGetSymbolAddress((void**)&S,   g_S);

    cudaFuncSetAttribute(gemm_fp16<3,0>, cudaFuncAttributeMaxDynamicSharedMemorySize, GSMEM);
    cudaFuncSetAttribute(gemm_fp16<0,0>, cudaFuncAttributeMaxDynamicSharedMemorySize, GSMEM);
    cudaFuncSetAttribute(gemm_fp16<2,1>, cudaFuncAttributeMaxDynamicSharedMemorySize, GSMEM);

    const size_t WSZ  = (size_t)ED * ED;
    const size_t QSZ  = (size_t)MTOT * ED;
    const size_t sQKV = (size_t)SEQ * ED;
    const size_t sS   = (size_t)SEQ * SEQ;
    __half* Qp = QKV;
    __half* Kp = QKV + QSZ;
    __half* Vp = QKV + 2 * QSZ;

    // 1) convert x + 4 weights to fp16 (one launch)
    {
        dim3 g(2048, 1, 5);
        conv_all_kernel<<<g, 256>>>(x, (const float*)d_in[1], (const float*)d_in[2],
                                    (const float*)d_in[3], (const float*)d_in[4],
                                    xh, Wh);
    }

    // 2) fused QKV projection: [8192, 3072] = xh @ [Wq;Wk;Wv]^T (1-pass)
    {
        dim3 grid((3 * ED) / BN, MTOT / BM, 1);
        gemm_fp16<3,0><<<grid, 256, GSMEM>>>(xh, Wh, nullptr, QKV,
                                             3 * ED, ED, 1.0f, 0, 0, 0);
    }

    // 3) scores S = Qp Kp^T / 32 (batched; 1-pass)
    {
        dim3 grid(SEQ / BN, SEQ / BM, NB);
        gemm_fp16<0,0><<<grid, 256, GSMEM>>>(Qp, Kp, S, nullptr,
                                             SEQ, ED, 0.03125f, sQKV, sQKV, sS);
    }

    // 4) softmax -> plain fp16 P
    softmax_row<<<NB * SEQ, 256>>>(S, Phi);

    // 5) O = P Vp (batched; 1-pass; V natural layout -> TRANSB)
    {
        dim3 grid(ED / BN, SEQ / BM, NB);
        gemm_fp16<2,1><<<grid, 256, GSMEM>>>(Phi, Vp, nullptr, Op,
                                             ED, SEQ, 1.0f, sS, sQKV, sQKV);
    }

    // 6) out = O Wo^T (M=8192, N=1024, K=1024; 1-pass), fp32 result
    {
        dim3 grid(ED / BN, MTOT / BM, 1);
        gemm_fp16<0,0><<<grid, 256, GSMEM>>>(Op, Wh + 3 * WSZ, out, nullptr,
                                             ED, ED, 1.0f, 0, 0, 0);
    }
}